// round 5
// baseline (speedup 1.0000x reference)
#include <cuda_runtime.h>
#include <cuda_bf16.h>
#include <math.h>
#include <stdint.h>

#define N_NODES 50000
#define N_EDGES 800000
#define D_IN    256
#define QKVS_W  1024
#define KAUG    768
#define KSTORE  512

typedef __nv_bfloat16 bf16;

// ---------------- scratch (device globals) ----------------
__device__ bf16  g_Waug1[KAUG * QKVS_W];               // augmented QKVS weights [768,1024]
__device__ bf16  g_Waug2[KAUG * 256];                  // augmented Wout [768,256]
__device__ float g_bcat[QKVS_W];
__device__ bf16  g_xaug[(size_t)N_NODES * KSTORE];     // augmented x [N,512] = [hi|lo]
__device__ float g_qkvs[(size_t)N_NODES * QKVS_W];     // Q|K|V|Skip per node (fp32)
__device__ bf16  g_maug[(size_t)N_NODES * KSTORE];     // augmented attention output [hi|lo]
__device__ float g_tmp[(size_t)N_NODES * 256];         // pre-LN output GEMM result
__device__ int   g_deg[N_NODES];
__device__ int   g_off[N_NODES];
__device__ int   g_cur[N_NODES];
__device__ int   g_srcs[N_EDGES];

__device__ __forceinline__ void split_bf16(float v, bf16& hi, bf16& lo) {
    hi = __float2bfloat16(v);
    lo = __float2bfloat16(v - __bfloat162float(hi));
}

// ---------------- prep: pack augmented weights, zero counters ----------------
__global__ void prep_w_kernel(const float* __restrict__ Wq, const float* __restrict__ Wk,
                              const float* __restrict__ Wv, const float* __restrict__ Ws,
                              const float* __restrict__ bq, const float* __restrict__ bk,
                              const float* __restrict__ bv, const float* __restrict__ bs,
                              const float* __restrict__ Wout)
{
    int idx = blockIdx.x * blockDim.x + threadIdx.x;
    if (idx < D_IN * QKVS_W) {
        int d  = idx >> 10;
        int o  = idx & 1023;
        int sec = o >> 8;
        int oo  = o & 255;
        int h   = oo >> 6;
        int kk  = oo & 63;
        const float* W = (sec == 0) ? Wq : (sec == 1) ? Wk : (sec == 2) ? Wv : Ws;
        float w = W[((h << 8) + d) * 64 + kk];
        bf16 hi, lo; split_bf16(w, hi, lo);
        g_Waug1[(size_t)d * QKVS_W + o] = hi;          // rows [0,256): hi   (pairs A-hi)
        g_Waug1[(size_t)(d + 256) * QKVS_W + o] = hi;  // rows [256,512): hi (pairs A-lo)
        g_Waug1[(size_t)(d + 512) * QKVS_W + o] = lo;  // rows [512,768): lo (pairs A-hi)
    }
    if (idx < 256 * 256) {
        int d = idx >> 8, o = idx & 255;
        float w = Wout[d * 256 + o];
        bf16 hi, lo; split_bf16(w, hi, lo);
        g_Waug2[(size_t)d * 256 + o] = hi;
        g_Waug2[(size_t)(d + 256) * 256 + o] = hi;
        g_Waug2[(size_t)(d + 512) * 256 + o] = lo;
    }
    if (idx < QKVS_W) {
        int sec = idx >> 8, oo = idx & 255;
        const float* b = (sec == 0) ? bq : (sec == 1) ? bk : (sec == 2) ? bv : bs;
        g_bcat[idx] = b[oo];
    }
    if (idx < N_NODES) { g_deg[idx] = 0; g_cur[idx] = 0; }
}

// x [N,256] fp32 -> xaug [N,512] bf16 ([hi|lo])
__global__ void conv_x_kernel(const float* __restrict__ x, int n_nodes)
{
    int idx = blockIdx.x * blockDim.x + threadIdx.x;   // over N*128 float2s
    if (idx >= n_nodes * 128) return;
    int n = idx >> 7;
    int c = (idx & 127) * 2;
    float2 v = *(const float2*)&x[(size_t)n * 256 + c];
    bf16 h0, l0, h1, l1;
    split_bf16(v.x, h0, l0);
    split_bf16(v.y, h1, l1);
    __nv_bfloat162 hp; hp.x = h0; hp.y = h1;
    __nv_bfloat162 lp; lp.x = l0; lp.y = l1;
    bf16* base = g_xaug + (size_t)n * KSTORE;
    *(__nv_bfloat162*)(base + c)       = hp;
    *(__nv_bfloat162*)(base + 256 + c) = lp;
}

// ---------------- tensor-core GEMM ----------------
// C[M,Nc] = Aaug[M,512->logical 768] * Baug[768,Nc] + bias
// A column remap: logical k >= 512 reads k-512 (hi again).
#define ASTRIDE 40
#define BSTRIDE 136

__device__ __forceinline__ void cp16(uint32_t s, const void* g) {
    asm volatile("cp.async.cg.shared.global [%0], [%1], 16;\n" :: "r"(s), "l"(g));
}
__device__ __forceinline__ uint32_t s2u(const void* p) {
    return (uint32_t)__cvta_generic_to_shared(p);
}

__global__ __launch_bounds__(256) void mma_gemm(
    const bf16* __restrict__ A, const bf16* __restrict__ B,
    const float* __restrict__ bias, float* __restrict__ C,
    int M, int Nc)
{
    __shared__ bf16 As[2][128][ASTRIDE];
    __shared__ bf16 Bs[2][32][BSTRIDE];

    int tid  = threadIdx.x;
    int warp = tid >> 5, lane = tid & 31;
    int wm = (warp >> 2) * 64;
    int wn = (warp & 3) * 32;
    int row0 = blockIdx.y * 128;
    int col0 = blockIdx.x * 128;

    float acc[4][4][4];
#pragma unroll
    for (int i = 0; i < 4; i++)
#pragma unroll
        for (int j = 0; j < 4; j++)
#pragma unroll
            for (int k = 0; k < 4; k++) acc[i][j][k] = 0.f;

    int ar = tid >> 2, aq = tid & 3;
    int br = tid >> 4, bq = tid & 15;

    // hoisted, clamped A row pointers
    const bf16* Arow0 = A + (size_t)min(row0 + ar, M - 1) * KSTORE + aq * 8;
    const bf16* Arow1 = A + (size_t)min(row0 + 64 + ar, M - 1) * KSTORE + aq * 8;

    const int NT = KAUG / 32;   // 24

    {
        int k0 = 0, buf = 0;
        cp16(s2u(&As[buf][ar][aq * 8]),      Arow0 + k0);
        cp16(s2u(&As[buf][64 + ar][aq * 8]), Arow1 + k0);
        cp16(s2u(&Bs[buf][br][bq * 8]),      B + (size_t)(k0 + br) * Nc + col0 + bq * 8);
        cp16(s2u(&Bs[buf][16 + br][bq * 8]), B + (size_t)(k0 + 16 + br) * Nc + col0 + bq * 8);
        asm volatile("cp.async.commit_group;\n");
    }

    for (int t = 0; t < NT; t++) {
        int buf = t & 1;
        if (t + 1 < NT) {
            int k0 = (t + 1) * 32, nb = (t + 1) & 1;
            int ka = (k0 < KSTORE) ? k0 : k0 - KSTORE;   // A column remap
            cp16(s2u(&As[nb][ar][aq * 8]),      Arow0 + ka);
            cp16(s2u(&As[nb][64 + ar][aq * 8]), Arow1 + ka);
            cp16(s2u(&Bs[nb][br][bq * 8]),      B + (size_t)(k0 + br) * Nc + col0 + bq * 8);
            cp16(s2u(&Bs[nb][16 + br][bq * 8]), B + (size_t)(k0 + 16 + br) * Nc + col0 + bq * 8);
            asm volatile("cp.async.commit_group;\n");
            asm volatile("cp.async.wait_group 1;\n");
        } else {
            asm volatile("cp.async.wait_group 0;\n");
        }
        __syncthreads();

#pragma unroll
        for (int kk = 0; kk < 32; kk += 16) {
            uint32_t af[4][4];
#pragma unroll
            for (int mt = 0; mt < 4; mt++) {
                uint32_t addr = s2u(&As[buf][wm + mt * 16 + (lane & 15)][kk + (lane >> 4) * 8]);
                asm volatile("ldmatrix.sync.aligned.m8n8.x4.shared.b16 {%0,%1,%2,%3}, [%4];"
                             : "=r"(af[mt][0]), "=r"(af[mt][1]), "=r"(af[mt][2]), "=r"(af[mt][3])
                             : "r"(addr));
            }
            uint32_t bfr[4][2];
#pragma unroll
            for (int nt = 0; nt < 4; nt++) {
                uint32_t addr = s2u(&Bs[buf][kk + (lane & 15)][wn + nt * 8]);
                asm volatile("ldmatrix.sync.aligned.m8n8.x2.trans.shared.b16 {%0,%1}, [%2];"
                             : "=r"(bfr[nt][0]), "=r"(bfr[nt][1]) : "r"(addr));
            }
#pragma unroll
            for (int mt = 0; mt < 4; mt++)
#pragma unroll
                for (int nt = 0; nt < 4; nt++) {
                    asm volatile(
                        "mma.sync.aligned.m16n8k16.row.col.f32.bf16.bf16.f32 "
                        "{%0,%1,%2,%3}, {%4,%5,%6,%7}, {%8,%9}, {%0,%1,%2,%3};"
                        : "+f"(acc[mt][nt][0]), "+f"(acc[mt][nt][1]),
                          "+f"(acc[mt][nt][2]), "+f"(acc[mt][nt][3])
                        : "r"(af[mt][0]), "r"(af[mt][1]), "r"(af[mt][2]), "r"(af[mt][3]),
                          "r"(bfr[nt][0]), "r"(bfr[nt][1]));
                }
        }
        __syncthreads();
    }

#pragma unroll
    for (int mt = 0; mt < 4; mt++) {
#pragma unroll
        for (int nt = 0; nt < 4; nt++) {
            int c = col0 + wn + nt * 8 + 2 * (lane & 3);
            float2 b2 = *(const float2*)&bias[c];
            int r0 = row0 + wm + mt * 16 + (lane >> 2);
            if (r0 < M) {
                float2 o; o.x = acc[mt][nt][0] + b2.x; o.y = acc[mt][nt][1] + b2.y;
                *(float2*)&C[(size_t)r0 * Nc + c] = o;
            }
            int r1 = r0 + 8;
            if (r1 < M) {
                float2 o; o.x = acc[mt][nt][2] + b2.x; o.y = acc[mt][nt][3] + b2.y;
                *(float2*)&C[(size_t)r1 * Nc + c] = o;
            }
        }
    }
}

// ---------------- CSR build ----------------
__global__ void hist_kernel(const int* __restrict__ dst, int E)
{
    int e = blockIdx.x * blockDim.x + threadIdx.x;
    if (e < E) atomicAdd(&g_deg[dst[e]], 1);
}

__global__ void scan_kernel(int n)
{
    __shared__ int warp_sums[32];
    int tid = threadIdx.x;
    int ch  = (n + 1023) / 1024;
    int begin = tid * ch, end = min(begin + ch, n);
    int s = 0;
    for (int i = begin; i < end; i++) s += g_deg[i];
    int lane = tid & 31, w = tid >> 5;
    int v = s;
#pragma unroll
    for (int o = 1; o < 32; o <<= 1) {
        int t = __shfl_up_sync(0xffffffffu, v, o);
        if (lane >= o) v += t;
    }
    if (lane == 31) warp_sums[w] = v;
    __syncthreads();
    if (w == 0) {
        int ws = warp_sums[lane];
#pragma unroll
        for (int o = 1; o < 32; o <<= 1) {
            int t = __shfl_up_sync(0xffffffffu, ws, o);
            if (lane >= o) ws += t;
        }
        warp_sums[lane] = ws;
    }
    __syncthreads();
    int run = v - s + (w ? warp_sums[w - 1] : 0);
    for (int i = begin; i < end; i++) { g_off[i] = run; run += g_deg[i]; }
}

__global__ void scatter_kernel(const int* __restrict__ src, const int* __restrict__ dst, int E)
{
    int e = blockIdx.x * blockDim.x + threadIdx.x;
    if (e < E) {
        int d = dst[e];
        int pos = g_off[d] + atomicAdd(&g_cur[d], 1);
        g_srcs[pos] = src[e];
    }
}

// ---------------- attention: half-warp-per-edge online softmax ----------------
// block = node, warp = head; 16 lanes own one edge, lane holds 4 dims (float4).
__global__ __launch_bounds__(128) void attn_kernel(int n_nodes)
{
    int n = blockIdx.x;
    int h    = threadIdx.x >> 5;
    int lane = threadIdx.x & 31;
    int hl   = lane & 15;        // lane within half
    int half = lane >> 4;        // 0 or 1

    int deg = g_deg[n];
    int off = g_off[n];

    const unsigned FULL = 0xffffffffu;
    const float NEG = -1e30f;

    const float* qrow = g_qkvs + (size_t)n * QKVS_W + h * 64;
    float4 q4 = *(const float4*)&qrow[hl * 4];

    float m = NEG, s = 0.f;
    float4 a4 = make_float4(0.f, 0.f, 0.f, 0.f);

    for (int base = 0; base < deg; base += 32) {
        int cnt = min(32, deg - base);
        int my = (lane < cnt) ? g_srcs[off + base + lane] : 0;

        for (int j = 0; j < cnt; j += 2) {
            int e = j + half;                      // this half's edge
            bool valid = (e < cnt);
            int src = __shfl_sync(FULL, my, e & 31);
            const float* kr = g_qkvs + (size_t)src * QKVS_W + 256 + h * 64;
            float4 k4 = *(const float4*)&kr[hl * 4];
            float4 v4 = *(const float4*)&kr[256 + hl * 4];

            float p = q4.x * k4.x + q4.y * k4.y + q4.z * k4.z + q4.w * k4.w;
            p += __shfl_xor_sync(FULL, p, 8);
            p += __shfl_xor_sync(FULL, p, 4);
            p += __shfl_xor_sync(FULL, p, 2);
            p += __shfl_xor_sync(FULL, p, 1);
            p *= 0.125f;                           // 1/sqrt(64)
            float pe = valid ? p : NEG;

            float nm = fmaxf(m, pe);
            float c  = __expf(m - nm);             // m,nm >= NEG finite -> no NaN
            float ea = valid ? __expf(p - nm) : 0.f;
            s    = s    * c + ea;
            a4.x = a4.x * c + ea * v4.x;
            a4.y = a4.y * c + ea * v4.y;
            a4.z = a4.z * c + ea * v4.z;
            a4.w = a4.w * c + ea * v4.w;
            m = nm;
        }
    }

    // merge the two halves (lanes l and l+16 hold the same dims)
    float  mo = __shfl_xor_sync(FULL, m, 16);
    float  so = __shfl_xor_sync(FULL, s, 16);
    float4 ao;
    ao.x = __shfl_xor_sync(FULL, a4.x, 16);
    ao.y = __shfl_xor_sync(FULL, a4.y, 16);
    ao.z = __shfl_xor_sync(FULL, a4.z, 16);
    ao.w = __shfl_xor_sync(FULL, a4.w, 16);

    float nm = fmaxf(m, mo);
    float c0 = __expf(m - nm), c1 = __expf(mo - nm);
    s    = s * c0 + so * c1;
    a4.x = a4.x * c0 + ao.x * c1;
    a4.y = a4.y * c0 + ao.y * c1;
    a4.z = a4.z * c0 + ao.z * c1;
    a4.w = a4.w * c0 + ao.w * c1;

    if (half == 0) {
        float inv = 1.f / (s + 1e-16f);
        float4 sk4 = *(const float4*)&g_qkvs[(size_t)n * QKVS_W + 768 + h * 64 + hl * 4];
        float o0 = a4.x * inv + sk4.x;
        float o1 = a4.y * inv + sk4.y;
        float o2 = a4.z * inv + sk4.z;
        float o3 = a4.w * inv + sk4.w;

        bf16 h0, l0, h1, l1, h2, l2, h3, l3;
        split_bf16(o0, h0, l0); split_bf16(o1, h1, l1);
        split_bf16(o2, h2, l2); split_bf16(o3, h3, l3);

        bf16* baseo = g_maug + (size_t)n * KSTORE;
        int c = h * 64 + hl * 4;
        __nv_bfloat162 hA; hA.x = h0; hA.y = h1;
        __nv_bfloat162 hB; hB.x = h2; hB.y = h3;
        __nv_bfloat162 lA; lA.x = l0; lA.y = l1;
        __nv_bfloat162 lB; lB.x = l2; lB.y = l3;
        *(__nv_bfloat162*)(baseo + c)           = hA;
        *(__nv_bfloat162*)(baseo + c + 2)       = hB;
        *(__nv_bfloat162*)(baseo + 256 + c)     = lA;
        *(__nv_bfloat162*)(baseo + 256 + c + 2) = lB;
    }
}

// ---------------- residual + LayerNorm ----------------
__global__ __launch_bounds__(256) void ln_kernel(const float* __restrict__ x,
                                                 const float* __restrict__ gamma,
                                                 const float* __restrict__ beta,
                                                 float* __restrict__ out, int n_nodes)
{
    int row  = blockIdx.x * 8 + (threadIdx.x >> 5);
    int lane = threadIdx.x & 31;
    if (row >= n_nodes) return;

    const float* t  = g_tmp + (size_t)row * 256;
    const float* xr = x + (size_t)row * 256;

    float h[8];
    float s = 0.f, s2 = 0.f;
#pragma unroll
    for (int i = 0; i < 8; i++) {
        int c = lane + 32 * i;
        h[i] = t[c] + xr[c];
        s  += h[i];
        s2 += h[i] * h[i];
    }
#pragma unroll
    for (int o = 16; o; o >>= 1) {
        s  += __shfl_xor_sync(0xffffffffu, s,  o);
        s2 += __shfl_xor_sync(0xffffffffu, s2, o);
    }
    float mu  = s * (1.f / 256.f);
    float var = s2 * (1.f / 256.f) - mu * mu;
    float r   = rsqrtf(var + 1e-5f);
#pragma unroll
    for (int i = 0; i < 8; i++) {
        int c = lane + 32 * i;
        out[(size_t)row * 256 + c] = (h[i] - mu) * r * gamma[c] + beta[c];
    }
}

// ---------------- launch ----------------
extern "C" void kernel_launch(void* const* d_in, const int* in_sizes, int n_in,
                              void* d_out, int out_size)
{
    const float* x     = (const float*)d_in[0];
    const int*   ei    = (const int*)d_in[1];
    const float* Wq    = (const float*)d_in[2];
    const float* bq    = (const float*)d_in[3];
    const float* Wk    = (const float*)d_in[4];
    const float* bk    = (const float*)d_in[5];
    const float* Wv    = (const float*)d_in[6];
    const float* bv    = (const float*)d_in[7];
    const float* Wsk   = (const float*)d_in[8];
    const float* bsk   = (const float*)d_in[9];
    const float* Wout  = (const float*)d_in[10];
    const float* bout  = (const float*)d_in[11];
    const float* ln_g  = (const float*)d_in[12];
    const float* ln_b  = (const float*)d_in[13];
    float* out = (float*)d_out;

    int N = in_sizes[0] / D_IN;
    int E = in_sizes[1] / 2;

    void* p;
    cudaGetSymbolAddress(&p, g_Waug1); bf16* Waug1 = (bf16*)p;
    cudaGetSymbolAddress(&p, g_Waug2); bf16* Waug2 = (bf16*)p;
    cudaGetSymbolAddress(&p, g_bcat);  float* bcat = (float*)p;
    cudaGetSymbolAddress(&p, g_xaug);  bf16* xaug  = (bf16*)p;
    cudaGetSymbolAddress(&p, g_qkvs);  float* qkvs = (float*)p;
    cudaGetSymbolAddress(&p, g_maug);  bf16* maug  = (bf16*)p;
    cudaGetSymbolAddress(&p, g_tmp);   float* tmp  = (float*)p;

    const int* srcs = ei;
    const int* dsts = ei + E;

    prep_w_kernel<<<(D_IN * QKVS_W + 255) / 256, 256>>>(Wq, Wk, Wv, Wsk, bq, bk, bv, bsk, Wout);
    conv_x_kernel<<<(N * 128 + 255) / 256, 256>>>(x, N);

    {
        dim3 grid(QKVS_W / 128, (N + 127) / 128);
        mma_gemm<<<grid, 256>>>(xaug, Waug1, bcat, qkvs, N, QKVS_W);
    }

    hist_kernel<<<(E + 255) / 256, 256>>>(dsts, E);
    scan_kernel<<<1, 1024>>>(N);
    scatter_kernel<<<(E + 255) / 256, 256>>>(srcs, dsts, E);

    attn_kernel<<<N, 128>>>(N);

    {
        dim3 grid(256 / 128, (N + 127) / 128);
        mma_gemm<<<grid, 256>>>(maug, Waug2, bout, tmp, N, 256);
    }

    ln_kernel<<<(N + 7) / 8, 256>>>(x, ln_g, ln_b, out, N);
}